// round 1
// baseline (speedup 1.0000x reference)
#include <cuda_runtime.h>
#include <math.h>

#define BB 32
#define NN 16384
#define KK 64
#define CHUNKS 32
#define ROWS_PER_CHUNK (NN / CHUNKS)   // 512

// Deterministic scratch: [tensor][b][chunk][k][4]  (sg, sx, sy, sz)
__device__ float g_partials[2 * BB * CHUNKS * KK * 4];

// ---------------------------------------------------------------------------
// Stage 1: per-chunk weighted reductions.
// Block = 256 threads: kg = tid&15 owns k in [4*kg, 4*kg+3] (one LDG.128/row),
// rg = tid>>4 strides rows. Fully coalesced gamma reads (1KB per block-row).
// ---------------------------------------------------------------------------
__global__ void __launch_bounds__(256, 8) stage1_kernel(
    const float* __restrict__ pts_x, const float* __restrict__ pts_y,
    const float* __restrict__ gam_x, const float* __restrict__ gam_y)
{
    const int chunk = blockIdx.x;
    const int b     = blockIdx.y;
    const int tsel  = blockIdx.z;
    const float* __restrict__ pts = tsel ? pts_y : pts_x;
    const float* __restrict__ gam = tsel ? gam_y : gam_x;

    const int tid = threadIdx.x;
    const int kg  = tid & 15;   // k4 group
    const int rg  = tid >> 4;   // row group 0..15

    float sg[4] = {0.f, 0.f, 0.f, 0.f};
    float sx[4] = {0.f, 0.f, 0.f, 0.f};
    float sy[4] = {0.f, 0.f, 0.f, 0.f};
    float sz[4] = {0.f, 0.f, 0.f, 0.f};

    const int n0 = chunk * ROWS_PER_CHUNK;

    #pragma unroll 4
    for (int r = rg; r < ROWS_PER_CHUNK; r += 16) {
        const size_t n = (size_t)b * NN + (size_t)(n0 + r);
        const float4 g = *reinterpret_cast<const float4*>(gam + n * KK + 4 * kg);
        const float px = pts[n * 3 + 0];
        const float py = pts[n * 3 + 1];
        const float pz = pts[n * 3 + 2];
        sg[0] += g.x; sg[1] += g.y; sg[2] += g.z; sg[3] += g.w;
        sx[0] = fmaf(g.x, px, sx[0]); sx[1] = fmaf(g.y, px, sx[1]);
        sx[2] = fmaf(g.z, px, sx[2]); sx[3] = fmaf(g.w, px, sx[3]);
        sy[0] = fmaf(g.x, py, sy[0]); sy[1] = fmaf(g.y, py, sy[1]);
        sy[2] = fmaf(g.z, py, sy[2]); sy[3] = fmaf(g.w, py, sy[3]);
        sz[0] = fmaf(g.x, pz, sz[0]); sz[1] = fmaf(g.y, pz, sz[1]);
        sz[2] = fmaf(g.z, pz, sz[2]); sz[3] = fmaf(g.w, pz, sz[3]);
    }

    // Block reduction across the 16 row-groups: smem[rg][k][val]
    __shared__ float smem[16 * KK * 4];
    #pragma unroll
    for (int j = 0; j < 4; ++j) {
        const int k = 4 * kg + j;
        float* p = &smem[(rg * KK + k) * 4];
        p[0] = sg[j]; p[1] = sx[j]; p[2] = sy[j]; p[3] = sz[j];
    }
    __syncthreads();

    // 256 threads == 64 k * 4 vals; tid = k*4 + val
    const int k   = tid >> 2;
    const int val = tid & 3;
    float acc = 0.f;
    #pragma unroll
    for (int r = 0; r < 16; ++r) acc += smem[(r * KK + k) * 4 + val];

    g_partials[(((size_t)tsel * BB + b) * CHUNKS + chunk) * (KK * 4) + tid] = acc;
}

// ---------------------------------------------------------------------------
// Stage 2: chunk reduction + weighted Procrustes + 3x3 SVD (double, thread 0).
// One block per batch, 64 threads (one per k).
// ---------------------------------------------------------------------------
__global__ void __launch_bounds__(64) stage2_kernel(float* __restrict__ out)
{
    const int b = blockIdx.x;
    const int k = threadIdx.x;   // 0..63

    double sgx = 0, sxx = 0, syx = 0, szx = 0;
    double sgy = 0, sxy = 0, syy = 0, szy = 0;
    for (int c = 0; c < CHUNKS; ++c) {
        const float* px = &g_partials[(((size_t)0 * BB + b) * CHUNKS + c) * (KK * 4) + k * 4];
        sgx += px[0]; sxx += px[1]; syx += px[2]; szx += px[3];
        const float* py = &g_partials[(((size_t)1 * BB + b) * CHUNKS + c) * (KK * 4) + k * 4];
        sgy += py[0]; sxy += py[1]; syy += py[2]; szy += py[3];
    }

    const double EPSd = 1e-8;
    const double pix = sgx / (double)NN;
    const double piy = sgy / (double)NN;
    double mux[3] = { sxx / (pix + EPSd), syx / (pix + EPSd), szx / (pix + EPSd) };
    double muy[3] = { sxy / (piy + EPSd), syy / (piy + EPSd), szy / (piy + EPSd) };
    const double w = pix * piy;

    __shared__ double red[64][9];
    __shared__ double bc[8];

    red[k][0] = w;
    red[k][1] = w * mux[0]; red[k][2] = w * mux[1]; red[k][3] = w * mux[2];
    red[k][4] = w * muy[0]; red[k][5] = w * muy[1]; red[k][6] = w * muy[2];
    red[k][7] = 0.0; red[k][8] = 0.0;
    __syncthreads();

    if (k == 0) {
        double s[7] = {0, 0, 0, 0, 0, 0, 0};
        for (int i = 0; i < 64; ++i)
            for (int j = 0; j < 7; ++j) s[j] += red[i][j];
        const double ws = s[0] + EPSd;
        bc[0] = s[1] / ws; bc[1] = s[2] / ws; bc[2] = s[3] / ws;   // c_s
        bc[3] = s[4] / ws; bc[4] = s[5] / ws; bc[5] = s[6] / ws;   // c_t
    }
    __syncthreads();

    const double s0 = mux[0] - bc[0], s1 = mux[1] - bc[1], s2 = mux[2] - bc[2];
    const double t0 = muy[0] - bc[3], t1 = muy[1] - bc[4], t2 = muy[2] - bc[5];
    red[k][0] = w * s0 * t0; red[k][1] = w * s0 * t1; red[k][2] = w * s0 * t2;
    red[k][3] = w * s1 * t0; red[k][4] = w * s1 * t1; red[k][5] = w * s1 * t2;
    red[k][6] = w * s2 * t0; red[k][7] = w * s2 * t1; red[k][8] = w * s2 * t2;
    __syncthreads();

    if (k == 0) {
        double H[3][3] = {{0, 0, 0}, {0, 0, 0}, {0, 0, 0}};
        for (int i = 0; i < 64; ++i) {
            H[0][0] += red[i][0]; H[0][1] += red[i][1]; H[0][2] += red[i][2];
            H[1][0] += red[i][3]; H[1][1] += red[i][4]; H[1][2] += red[i][5];
            H[2][0] += red[i][6]; H[2][1] += red[i][7]; H[2][2] += red[i][8];
        }

        // A = H^T H (symmetric)
        double A[3][3];
        for (int i = 0; i < 3; ++i)
            for (int j = 0; j < 3; ++j)
                A[i][j] = H[0][i] * H[0][j] + H[1][i] * H[1][j] + H[2][i] * H[2][j];

        double V[3][3] = {{1, 0, 0}, {0, 1, 0}, {0, 0, 1}};
        // Cyclic Jacobi
        for (int sweep = 0; sweep < 30; ++sweep) {
            const double off = fabs(A[0][1]) + fabs(A[0][2]) + fabs(A[1][2]);
            const double diag = fabs(A[0][0]) + fabs(A[1][1]) + fabs(A[2][2]);
            if (off <= 1e-15 * (diag + 1e-300)) break;
            const int PQ[3][2] = {{0, 1}, {0, 2}, {1, 2}};
            for (int m = 0; m < 3; ++m) {
                const int p = PQ[m][0], q = PQ[m][1];
                const double apq = A[p][q];
                if (fabs(apq) < 1e-300) continue;
                const double tau = (A[q][q] - A[p][p]) / (2.0 * apq);
                const double tt = (tau >= 0.0 ? 1.0 : -1.0) /
                                  (fabs(tau) + sqrt(1.0 + tau * tau));
                const double c = 1.0 / sqrt(1.0 + tt * tt);
                const double s = tt * c;
                const double app = A[p][p], aqq = A[q][q];
                A[p][p] = app - tt * apq;
                A[q][q] = aqq + tt * apq;
                A[p][q] = A[q][p] = 0.0;
                const int r = 3 - p - q;
                const double arp = A[r][p], arq = A[r][q];
                A[r][p] = A[p][r] = c * arp - s * arq;
                A[r][q] = A[q][r] = s * arp + c * arq;
                for (int i = 0; i < 3; ++i) {
                    const double vip = V[i][p], viq = V[i][q];
                    V[i][p] = c * vip - s * viq;
                    V[i][q] = s * vip + c * viq;
                }
            }
        }

        double eig[3] = {A[0][0], A[1][1], A[2][2]};
        // Sort descending, permuting V columns
        for (int i = 0; i < 2; ++i)
            for (int j = i + 1; j < 3; ++j)
                if (eig[j] > eig[i]) {
                    double tmp = eig[i]; eig[i] = eig[j]; eig[j] = tmp;
                    for (int r = 0; r < 3; ++r) {
                        tmp = V[r][i]; V[r][i] = V[r][j]; V[r][j] = tmp;
                    }
                }

        // U columns: u0 = normalize(H v0); u1 = GS-orthonormalize(H v1); u2 = u0 x u1
        double U[3][3];
        {
            double u0[3], u1[3];
            for (int i = 0; i < 3; ++i)
                u0[i] = H[i][0] * V[0][0] + H[i][1] * V[1][0] + H[i][2] * V[2][0];
            double n0 = sqrt(u0[0] * u0[0] + u0[1] * u0[1] + u0[2] * u0[2]);
            if (n0 > 1e-150) { u0[0] /= n0; u0[1] /= n0; u0[2] /= n0; }
            else { u0[0] = 1; u0[1] = 0; u0[2] = 0; }

            for (int i = 0; i < 3; ++i)
                u1[i] = H[i][0] * V[0][1] + H[i][1] * V[1][1] + H[i][2] * V[2][1];
            const double d01 = u1[0] * u0[0] + u1[1] * u0[1] + u1[2] * u0[2];
            u1[0] -= d01 * u0[0]; u1[1] -= d01 * u0[1]; u1[2] -= d01 * u0[2];
            double n1 = sqrt(u1[0] * u1[0] + u1[1] * u1[1] + u1[2] * u1[2]);
            if (n1 > 1e-150) { u1[0] /= n1; u1[1] /= n1; u1[2] /= n1; }
            else {
                // pick any unit vector orthogonal to u0
                double ax = fabs(u0[0]), ay = fabs(u0[1]), az = fabs(u0[2]);
                double e[3] = {0, 0, 0};
                if (ax <= ay && ax <= az) e[0] = 1;
                else if (ay <= az) e[1] = 1;
                else e[2] = 1;
                u1[0] = u0[1] * e[2] - u0[2] * e[1];
                u1[1] = u0[2] * e[0] - u0[0] * e[2];
                u1[2] = u0[0] * e[1] - u0[1] * e[0];
                double nn = sqrt(u1[0] * u1[0] + u1[1] * u1[1] + u1[2] * u1[2]);
                u1[0] /= nn; u1[1] /= nn; u1[2] /= nn;
            }
            double u2[3] = { u0[1] * u1[2] - u0[2] * u1[1],
                             u0[2] * u1[0] - u0[0] * u1[2],
                             u0[0] * u1[1] - u0[1] * u1[0] };
            for (int i = 0; i < 3; ++i) {
                U[i][0] = u0[i]; U[i][1] = u1[i]; U[i][2] = u2[i];
            }
        }

        const double detV =
            V[0][0] * (V[1][1] * V[2][2] - V[1][2] * V[2][1]) -
            V[0][1] * (V[1][0] * V[2][2] - V[1][2] * V[2][0]) +
            V[0][2] * (V[1][0] * V[2][1] - V[1][1] * V[2][0]);
        const double detU =
            U[0][0] * (U[1][1] * U[2][2] - U[1][2] * U[2][1]) -
            U[0][1] * (U[1][0] * U[2][2] - U[1][2] * U[2][0]) +
            U[0][2] * (U[1][0] * U[2][1] - U[1][1] * U[2][0]);
        const double d = detV * detU;   // det(V U^T)

        // R = V diag(1,1,d) U^T
        double R[3][3];
        for (int i = 0; i < 3; ++i)
            for (int j = 0; j < 3; ++j)
                R[i][j] = V[i][0] * U[j][0] + V[i][1] * U[j][1] + d * V[i][2] * U[j][2];

        // t = c_t - R c_s
        double tv[3];
        for (int i = 0; i < 3; ++i)
            tv[i] = bc[3 + i] - (R[i][0] * bc[0] + R[i][1] * bc[1] + R[i][2] * bc[2]);

        // Output: R (B*9) then t (B*3)
        for (int i = 0; i < 3; ++i)
            for (int j = 0; j < 3; ++j)
                out[b * 9 + i * 3 + j] = (float)R[i][j];
        for (int i = 0; i < 3; ++i)
            out[BB * 9 + b * 3 + i] = (float)tv[i];
    }
}

extern "C" void kernel_launch(void* const* d_in, const int* in_sizes, int n_in,
                              void* d_out, int out_size)
{
    const float* pts_x = (const float*)d_in[0];
    const float* pts_y = (const float*)d_in[1];
    const float* gam_x = (const float*)d_in[2];
    const float* gam_y = (const float*)d_in[3];

    dim3 grid1(CHUNKS, BB, 2);
    stage1_kernel<<<grid1, 256>>>(pts_x, pts_y, gam_x, gam_y);
    stage2_kernel<<<BB, KK>>>((float*)d_out);
}

// round 2
// speedup vs baseline: 2.4896x; 2.4896x over previous
#include <cuda_runtime.h>
#include <math.h>

#define BB 32
#define NN 16384
#define KK 64
#define CHUNKS 16
#define ROWS_PER_CHUNK (NN / CHUNKS)   // 1024

// Deterministic scratch: [tensor][b][chunk][k][4]  (sg, sx, sy, sz)
__device__ float g_partials[2 * BB * CHUNKS * KK * 4];

// ---------------------------------------------------------------------------
// Stage 1: per-chunk weighted reductions (pure HBM streaming).
// Block = 256 threads: kg = tid&15 owns k in [4*kg, 4*kg+3] (one LDG.128/row),
// rg = tid>>4 strides rows. Fully coalesced gamma reads (1KB per block-row).
// ---------------------------------------------------------------------------
__global__ void __launch_bounds__(256, 8) stage1_kernel(
    const float* __restrict__ pts_x, const float* __restrict__ pts_y,
    const float* __restrict__ gam_x, const float* __restrict__ gam_y)
{
    const int chunk = blockIdx.x;
    const int b     = blockIdx.y;
    const int tsel  = blockIdx.z;
    const float* __restrict__ pts = tsel ? pts_y : pts_x;
    const float* __restrict__ gam = tsel ? gam_y : gam_x;

    const int tid = threadIdx.x;
    const int kg  = tid & 15;   // k4 group
    const int rg  = tid >> 4;   // row group 0..15

    float sg[4] = {0.f, 0.f, 0.f, 0.f};
    float sx[4] = {0.f, 0.f, 0.f, 0.f};
    float sy[4] = {0.f, 0.f, 0.f, 0.f};
    float sz[4] = {0.f, 0.f, 0.f, 0.f};

    const int n0 = chunk * ROWS_PER_CHUNK;

    #pragma unroll 4
    for (int r = rg; r < ROWS_PER_CHUNK; r += 16) {
        const size_t n = (size_t)b * NN + (size_t)(n0 + r);
        const float4 g = *reinterpret_cast<const float4*>(gam + n * KK + 4 * kg);
        const float px = pts[n * 3 + 0];
        const float py = pts[n * 3 + 1];
        const float pz = pts[n * 3 + 2];
        sg[0] += g.x; sg[1] += g.y; sg[2] += g.z; sg[3] += g.w;
        sx[0] = fmaf(g.x, px, sx[0]); sx[1] = fmaf(g.y, px, sx[1]);
        sx[2] = fmaf(g.z, px, sx[2]); sx[3] = fmaf(g.w, px, sx[3]);
        sy[0] = fmaf(g.x, py, sy[0]); sy[1] = fmaf(g.y, py, sy[1]);
        sy[2] = fmaf(g.z, py, sy[2]); sy[3] = fmaf(g.w, py, sy[3]);
        sz[0] = fmaf(g.x, pz, sz[0]); sz[1] = fmaf(g.y, pz, sz[1]);
        sz[2] = fmaf(g.z, pz, sz[2]); sz[3] = fmaf(g.w, pz, sz[3]);
    }

    // Block reduction across the 16 row-groups: smem[rg][k][val]
    __shared__ float smem[16 * KK * 4];
    #pragma unroll
    for (int j = 0; j < 4; ++j) {
        const int k = 4 * kg + j;
        float* p = &smem[(rg * KK + k) * 4];
        p[0] = sg[j]; p[1] = sx[j]; p[2] = sy[j]; p[3] = sz[j];
    }
    __syncthreads();

    // 256 threads == 64 k * 4 vals; tid = k*4 + val
    const int k   = tid >> 2;
    const int val = tid & 3;
    float acc = 0.f;
    #pragma unroll
    for (int r = 0; r < 16; ++r) acc += smem[(r * KK + k) * 4 + val];

    g_partials[(((size_t)tsel * BB + b) * CHUNKS + chunk) * (KK * 4) + tid] = acc;
}

// ---------------------------------------------------------------------------
// Stage 2: chunk reduction + weighted Procrustes + 3x3 SVD, all fp32.
// One block per batch, 64 threads (one per k); serial tail on thread 0.
// ---------------------------------------------------------------------------
__global__ void __launch_bounds__(64) stage2_kernel(float* __restrict__ out)
{
    const int b = blockIdx.x;
    const int k = threadIdx.x;   // 0..63

    float sgx = 0.f, sxx = 0.f, syx = 0.f, szx = 0.f;
    float sgy = 0.f, sxy = 0.f, syy = 0.f, szy = 0.f;
    #pragma unroll
    for (int c = 0; c < CHUNKS; ++c) {
        const float4 px = *reinterpret_cast<const float4*>(
            &g_partials[(((size_t)0 * BB + b) * CHUNKS + c) * (KK * 4) + k * 4]);
        sgx += px.x; sxx += px.y; syx += px.z; szx += px.w;
        const float4 py = *reinterpret_cast<const float4*>(
            &g_partials[(((size_t)1 * BB + b) * CHUNKS + c) * (KK * 4) + k * 4]);
        sgy += py.x; sxy += py.y; syy += py.z; szy += py.w;
    }

    const float EPSf = 1e-8f;
    const float pix = sgx * (1.0f / (float)NN);
    const float piy = sgy * (1.0f / (float)NN);
    const float rpx = 1.0f / (pix + EPSf);
    const float rpy = 1.0f / (piy + EPSf);
    float mux[3] = { sxx * rpx, syx * rpx, szx * rpx };
    float muy[3] = { sxy * rpy, syy * rpy, szy * rpy };
    const float w = pix * piy;

    __shared__ float red[64][9];
    __shared__ float bc[8];

    red[k][0] = w;
    red[k][1] = w * mux[0]; red[k][2] = w * mux[1]; red[k][3] = w * mux[2];
    red[k][4] = w * muy[0]; red[k][5] = w * muy[1]; red[k][6] = w * muy[2];
    __syncthreads();

    if (k == 0) {
        float s[7] = {0, 0, 0, 0, 0, 0, 0};
        for (int i = 0; i < 64; ++i) {
            #pragma unroll
            for (int j = 0; j < 7; ++j) s[j] += red[i][j];
        }
        const float ws = 1.0f / (s[0] + EPSf);
        bc[0] = s[1] * ws; bc[1] = s[2] * ws; bc[2] = s[3] * ws;   // c_s
        bc[3] = s[4] * ws; bc[4] = s[5] * ws; bc[5] = s[6] * ws;   // c_t
    }
    __syncthreads();

    const float s0 = mux[0] - bc[0], s1 = mux[1] - bc[1], s2 = mux[2] - bc[2];
    const float t0 = muy[0] - bc[3], t1 = muy[1] - bc[4], t2 = muy[2] - bc[5];
    red[k][0] = w * s0 * t0; red[k][1] = w * s0 * t1; red[k][2] = w * s0 * t2;
    red[k][3] = w * s1 * t0; red[k][4] = w * s1 * t1; red[k][5] = w * s1 * t2;
    red[k][6] = w * s2 * t0; red[k][7] = w * s2 * t1; red[k][8] = w * s2 * t2;
    __syncthreads();

    if (k == 0) {
        float H[3][3] = {{0, 0, 0}, {0, 0, 0}, {0, 0, 0}};
        for (int i = 0; i < 64; ++i) {
            H[0][0] += red[i][0]; H[0][1] += red[i][1]; H[0][2] += red[i][2];
            H[1][0] += red[i][3]; H[1][1] += red[i][4]; H[1][2] += red[i][5];
            H[2][0] += red[i][6]; H[2][1] += red[i][7]; H[2][2] += red[i][8];
        }

        // Scale H to O(1) so fp32 HtH Jacobi has healthy relative precision.
        float hmax = 0.f;
        for (int i = 0; i < 3; ++i)
            for (int j = 0; j < 3; ++j) hmax = fmaxf(hmax, fabsf(H[i][j]));
        const float hscale = (hmax > 1e-30f) ? (1.0f / hmax) : 1.0f;
        float Hs[3][3];
        for (int i = 0; i < 3; ++i)
            for (int j = 0; j < 3; ++j) Hs[i][j] = H[i][j] * hscale;

        // A = Hs^T Hs (symmetric)
        float A[3][3];
        for (int i = 0; i < 3; ++i)
            for (int j = 0; j < 3; ++j)
                A[i][j] = Hs[0][i] * Hs[0][j] + Hs[1][i] * Hs[1][j] + Hs[2][i] * Hs[2][j];

        float V[3][3] = {{1, 0, 0}, {0, 1, 0}, {0, 0, 1}};
        // Cyclic Jacobi, fixed sweep count (fp32, MUFU div/rsqrt)
        #pragma unroll 1
        for (int sweep = 0; sweep < 12; ++sweep) {
            const int PQ[3][2] = {{0, 1}, {0, 2}, {1, 2}};
            #pragma unroll
            for (int m = 0; m < 3; ++m) {
                const int p = PQ[m][0], q = PQ[m][1];
                const float apq = A[p][q];
                if (fabsf(apq) < 1e-35f) continue;
                const float tau = (A[q][q] - A[p][p]) / (2.0f * apq);
                const float tt  = copysignf(1.0f, tau) /
                                  (fabsf(tau) + sqrtf(1.0f + tau * tau));
                const float c = rsqrtf(1.0f + tt * tt);
                const float s = tt * c;
                const float app = A[p][p], aqq = A[q][q];
                A[p][p] = app - tt * apq;
                A[q][q] = aqq + tt * apq;
                A[p][q] = A[q][p] = 0.0f;
                const int r = 3 - p - q;
                const float arp = A[r][p], arq = A[r][q];
                A[r][p] = A[p][r] = c * arp - s * arq;
                A[r][q] = A[q][r] = s * arp + c * arq;
                #pragma unroll
                for (int i = 0; i < 3; ++i) {
                    const float vip = V[i][p], viq = V[i][q];
                    V[i][p] = c * vip - s * viq;
                    V[i][q] = s * vip + c * viq;
                }
            }
        }

        float eig[3] = {A[0][0], A[1][1], A[2][2]};
        // Sort descending, permuting V columns
        #pragma unroll
        for (int i = 0; i < 2; ++i)
            #pragma unroll
            for (int j = i + 1; j < 3; ++j)
                if (eig[j] > eig[i]) {
                    float tmp = eig[i]; eig[i] = eig[j]; eig[j] = tmp;
                    for (int r = 0; r < 3; ++r) {
                        tmp = V[r][i]; V[r][i] = V[r][j]; V[r][j] = tmp;
                    }
                }

        // U columns: u0 = normalize(Hs v0); u1 = GS(Hs v1); u2 = u0 x u1
        float U[3][3];
        {
            float u0[3], u1[3];
            for (int i = 0; i < 3; ++i)
                u0[i] = Hs[i][0] * V[0][0] + Hs[i][1] * V[1][0] + Hs[i][2] * V[2][0];
            float n0 = sqrtf(u0[0] * u0[0] + u0[1] * u0[1] + u0[2] * u0[2]);
            if (n0 > 1e-20f) { const float r = 1.0f / n0; u0[0] *= r; u0[1] *= r; u0[2] *= r; }
            else { u0[0] = 1; u0[1] = 0; u0[2] = 0; }

            for (int i = 0; i < 3; ++i)
                u1[i] = Hs[i][0] * V[0][1] + Hs[i][1] * V[1][1] + Hs[i][2] * V[2][1];
            const float d01 = u1[0] * u0[0] + u1[1] * u0[1] + u1[2] * u0[2];
            u1[0] -= d01 * u0[0]; u1[1] -= d01 * u0[1]; u1[2] -= d01 * u0[2];
            float n1 = sqrtf(u1[0] * u1[0] + u1[1] * u1[1] + u1[2] * u1[2]);
            if (n1 > 1e-20f) { const float r = 1.0f / n1; u1[0] *= r; u1[1] *= r; u1[2] *= r; }
            else {
                // pick any unit vector orthogonal to u0
                const float ax = fabsf(u0[0]), ay = fabsf(u0[1]), az = fabsf(u0[2]);
                float e[3] = {0, 0, 0};
                if (ax <= ay && ax <= az) e[0] = 1;
                else if (ay <= az) e[1] = 1;
                else e[2] = 1;
                u1[0] = u0[1] * e[2] - u0[2] * e[1];
                u1[1] = u0[2] * e[0] - u0[0] * e[2];
                u1[2] = u0[0] * e[1] - u0[1] * e[0];
                const float nn = rsqrtf(u1[0] * u1[0] + u1[1] * u1[1] + u1[2] * u1[2]);
                u1[0] *= nn; u1[1] *= nn; u1[2] *= nn;
            }
            const float u2[3] = { u0[1] * u1[2] - u0[2] * u1[1],
                                  u0[2] * u1[0] - u0[0] * u1[2],
                                  u0[0] * u1[1] - u0[1] * u1[0] };
            for (int i = 0; i < 3; ++i) {
                U[i][0] = u0[i]; U[i][1] = u1[i]; U[i][2] = u2[i];
            }
        }

        const float detV =
            V[0][0] * (V[1][1] * V[2][2] - V[1][2] * V[2][1]) -
            V[0][1] * (V[1][0] * V[2][2] - V[1][2] * V[2][0]) +
            V[0][2] * (V[1][0] * V[2][1] - V[1][1] * V[2][0]);
        const float detU =
            U[0][0] * (U[1][1] * U[2][2] - U[1][2] * U[2][1]) -
            U[0][1] * (U[1][0] * U[2][2] - U[1][2] * U[2][0]) +
            U[0][2] * (U[1][0] * U[2][1] - U[1][1] * U[2][0]);
        const float d = detV * detU;   // det(V U^T)

        // R = V diag(1,1,d) U^T
        float R[3][3];
        for (int i = 0; i < 3; ++i)
            for (int j = 0; j < 3; ++j)
                R[i][j] = V[i][0] * U[j][0] + V[i][1] * U[j][1] + d * V[i][2] * U[j][2];

        // t = c_t - R c_s
        float tv[3];
        for (int i = 0; i < 3; ++i)
            tv[i] = bc[3 + i] - (R[i][0] * bc[0] + R[i][1] * bc[1] + R[i][2] * bc[2]);

        // Output: R (B*9) then t (B*3)
        for (int i = 0; i < 3; ++i)
            for (int j = 0; j < 3; ++j)
                out[b * 9 + i * 3 + j] = R[i][j];
        for (int i = 0; i < 3; ++i)
            out[BB * 9 + b * 3 + i] = tv[i];
    }
}

extern "C" void kernel_launch(void* const* d_in, const int* in_sizes, int n_in,
                              void* d_out, int out_size)
{
    const float* pts_x = (const float*)d_in[0];
    const float* pts_y = (const float*)d_in[1];
    const float* gam_x = (const float*)d_in[2];
    const float* gam_y = (const float*)d_in[3];

    dim3 grid1(CHUNKS, BB, 2);
    stage1_kernel<<<grid1, 256>>>(pts_x, pts_y, gam_x, gam_y);
    stage2_kernel<<<BB, KK>>>((float*)d_out);
}

// round 3
// speedup vs baseline: 2.6429x; 1.0616x over previous
#include <cuda_runtime.h>
#include <math.h>

#define BB 32
#define NN 16384
#define KK 64
#define CHUNKS 16
#define ROWS_PER_CHUNK (NN / CHUNKS)   // 1024

// Deterministic scratch: [tensor][b][chunk][k][4]  (sg, sx, sy, sz)
__device__ float g_partials[2 * BB * CHUNKS * KK * 4];

// ---------------------------------------------------------------------------
// Stage 1: per-chunk weighted reductions (pure HBM streaming).
// Block = 256 threads: kg = tid&15 owns k in [4*kg, 4*kg+3] (one LDG.128/row),
// rg = tid>>4 strides rows. Fully coalesced gamma reads (1KB per block-row).
// ---------------------------------------------------------------------------
__global__ void __launch_bounds__(256, 8) stage1_kernel(
    const float* __restrict__ pts_x, const float* __restrict__ pts_y,
    const float* __restrict__ gam_x, const float* __restrict__ gam_y)
{
    const int chunk = blockIdx.x;
    const int b     = blockIdx.y;
    const int tsel  = blockIdx.z;
    const float* __restrict__ pts = tsel ? pts_y : pts_x;
    const float* __restrict__ gam = tsel ? gam_y : gam_x;

    const int tid = threadIdx.x;
    const int kg  = tid & 15;   // k4 group
    const int rg  = tid >> 4;   // row group 0..15

    float sg[4] = {0.f, 0.f, 0.f, 0.f};
    float sx[4] = {0.f, 0.f, 0.f, 0.f};
    float sy[4] = {0.f, 0.f, 0.f, 0.f};
    float sz[4] = {0.f, 0.f, 0.f, 0.f};

    const int n0 = chunk * ROWS_PER_CHUNK;

    #pragma unroll 4
    for (int r = rg; r < ROWS_PER_CHUNK; r += 16) {
        const size_t n = (size_t)b * NN + (size_t)(n0 + r);
        // gamma is streamed once: evict-first so it never thrashes L2
        const float4 g = __ldcs(reinterpret_cast<const float4*>(gam + n * KK + 4 * kg));
        const float px = __ldg(pts + n * 3 + 0);
        const float py = __ldg(pts + n * 3 + 1);
        const float pz = __ldg(pts + n * 3 + 2);
        sg[0] += g.x; sg[1] += g.y; sg[2] += g.z; sg[3] += g.w;
        sx[0] = fmaf(g.x, px, sx[0]); sx[1] = fmaf(g.y, px, sx[1]);
        sx[2] = fmaf(g.z, px, sx[2]); sx[3] = fmaf(g.w, px, sx[3]);
        sy[0] = fmaf(g.x, py, sy[0]); sy[1] = fmaf(g.y, py, sy[1]);
        sy[2] = fmaf(g.z, py, sy[2]); sy[3] = fmaf(g.w, py, sy[3]);
        sz[0] = fmaf(g.x, pz, sz[0]); sz[1] = fmaf(g.y, pz, sz[1]);
        sz[2] = fmaf(g.z, pz, sz[2]); sz[3] = fmaf(g.w, pz, sz[3]);
    }

    // Block reduction across the 16 row-groups: smem[rg][k][val]
    __shared__ float smem[16 * KK * 4];
    #pragma unroll
    for (int j = 0; j < 4; ++j) {
        const int k = 4 * kg + j;
        float* p = &smem[(rg * KK + k) * 4];
        p[0] = sg[j]; p[1] = sx[j]; p[2] = sy[j]; p[3] = sz[j];
    }
    __syncthreads();

    // 256 threads == 64 k * 4 vals; tid = k*4 + val
    const int k   = tid >> 2;
    const int val = tid & 3;
    float acc = 0.f;
    #pragma unroll
    for (int r = 0; r < 16; ++r) acc += smem[(r * KK + k) * 4 + val];

    g_partials[(((size_t)tsel * BB + b) * CHUNKS + chunk) * (KK * 4) + tid] = acc;
}

// ---------------------------------------------------------------------------
// Stage 2: chunk reduction + weighted Procrustes + 3x3 SVD, all fp32.
// One block per batch, 64 threads (one per k).
// Block reductions via warp shuffles; serial SVD tail on thread 0 with MUFU.
// ---------------------------------------------------------------------------
__device__ __forceinline__ void warp_reduce_n(float* v, int n)
{
    for (int o = 16; o; o >>= 1)
        for (int j = 0; j < n; ++j)
            v[j] += __shfl_xor_sync(0xffffffffu, v[j], o);
}

__global__ void __launch_bounds__(64) stage2_kernel(float* __restrict__ out)
{
    const int b    = blockIdx.x;
    const int k    = threadIdx.x;   // 0..63
    const int wid  = k >> 5;
    const int lane = k & 31;

    float sgx = 0.f, sxx = 0.f, syx = 0.f, szx = 0.f;
    float sgy = 0.f, sxy = 0.f, syy = 0.f, szy = 0.f;
    #pragma unroll
    for (int c = 0; c < CHUNKS; ++c) {
        const float4 px = *reinterpret_cast<const float4*>(
            &g_partials[(((size_t)0 * BB + b) * CHUNKS + c) * (KK * 4) + k * 4]);
        sgx += px.x; sxx += px.y; syx += px.z; szx += px.w;
        const float4 py = *reinterpret_cast<const float4*>(
            &g_partials[(((size_t)1 * BB + b) * CHUNKS + c) * (KK * 4) + k * 4]);
        sgy += py.x; sxy += py.y; syy += py.z; szy += py.w;
    }

    const float EPSf = 1e-8f;
    const float pix = sgx * (1.0f / (float)NN);
    const float piy = sgy * (1.0f / (float)NN);
    const float rpx = __fdividef(1.0f, pix + EPSf);
    const float rpy = __fdividef(1.0f, piy + EPSf);
    float mux[3] = { sxx * rpx, syx * rpx, szx * rpx };
    float muy[3] = { sxy * rpy, syy * rpy, szy * rpy };
    const float w = pix * piy;

    __shared__ float wsum[2][9];
    __shared__ float bc[8];

    // --- Reduction 1: weighted centroids (7 values) ---
    {
        float v[7] = { w, w * mux[0], w * mux[1], w * mux[2],
                          w * muy[0], w * muy[1], w * muy[2] };
        warp_reduce_n(v, 7);
        if (lane == 0)
            #pragma unroll
            for (int j = 0; j < 7; ++j) wsum[wid][j] = v[j];
    }
    __syncthreads();
    if (k == 0) {
        const float ws = __fdividef(1.0f, wsum[0][0] + wsum[1][0] + EPSf);
        #pragma unroll
        for (int j = 0; j < 6; ++j)
            bc[j] = (wsum[0][j + 1] + wsum[1][j + 1]) * ws;   // c_s then c_t
    }
    __syncthreads();

    // --- Reduction 2: weighted covariance H (9 values) ---
    const float s0 = mux[0] - bc[0], s1 = mux[1] - bc[1], s2 = mux[2] - bc[2];
    const float t0 = muy[0] - bc[3], t1 = muy[1] - bc[4], t2 = muy[2] - bc[5];
    {
        float v[9] = { w * s0 * t0, w * s0 * t1, w * s0 * t2,
                       w * s1 * t0, w * s1 * t1, w * s1 * t2,
                       w * s2 * t0, w * s2 * t1, w * s2 * t2 };
        warp_reduce_n(v, 9);
        if (lane == 0)
            #pragma unroll
            for (int j = 0; j < 9; ++j) wsum[wid][j] = v[j];
    }
    __syncthreads();

    if (k == 0) {
        float H[3][3];
        #pragma unroll
        for (int i = 0; i < 3; ++i)
            #pragma unroll
            for (int j = 0; j < 3; ++j)
                H[i][j] = wsum[0][i * 3 + j] + wsum[1][i * 3 + j];

        // Scale H to O(1) so fp32 HtH Jacobi has healthy relative precision.
        float hmax = 0.f;
        for (int i = 0; i < 3; ++i)
            for (int j = 0; j < 3; ++j) hmax = fmaxf(hmax, fabsf(H[i][j]));
        const float hscale = (hmax > 1e-30f) ? __fdividef(1.0f, hmax) : 1.0f;
        float Hs[3][3];
        for (int i = 0; i < 3; ++i)
            for (int j = 0; j < 3; ++j) Hs[i][j] = H[i][j] * hscale;

        // A = Hs^T Hs (symmetric)
        float A[3][3];
        for (int i = 0; i < 3; ++i)
            for (int j = 0; j < 3; ++j)
                A[i][j] = Hs[0][i] * Hs[0][j] + Hs[1][i] * Hs[1][j] + Hs[2][i] * Hs[2][j];

        float V[3][3] = {{1, 0, 0}, {0, 1, 0}, {0, 0, 1}};
        // Cyclic Jacobi, 6 sweeps (quadratic convergence; fp32 noise by ~4)
        #pragma unroll 1
        for (int sweep = 0; sweep < 6; ++sweep) {
            const int PQ[3][2] = {{0, 1}, {0, 2}, {1, 2}};
            #pragma unroll
            for (int m = 0; m < 3; ++m) {
                const int p = PQ[m][0], q = PQ[m][1];
                const float apq = A[p][q];
                if (fabsf(apq) < 1e-35f) continue;
                const float tau = __fdividef(A[q][q] - A[p][p], 2.0f * apq);
                const float tt  = __fdividef(copysignf(1.0f, tau),
                                  fabsf(tau) + sqrtf(1.0f + tau * tau));
                const float c = rsqrtf(1.0f + tt * tt);
                const float s = tt * c;
                const float app = A[p][p], aqq = A[q][q];
                A[p][p] = app - tt * apq;
                A[q][q] = aqq + tt * apq;
                A[p][q] = A[q][p] = 0.0f;
                const int r = 3 - p - q;
                const float arp = A[r][p], arq = A[r][q];
                A[r][p] = A[p][r] = c * arp - s * arq;
                A[r][q] = A[q][r] = s * arp + c * arq;
                #pragma unroll
                for (int i = 0; i < 3; ++i) {
                    const float vip = V[i][p], viq = V[i][q];
                    V[i][p] = c * vip - s * viq;
                    V[i][q] = s * vip + c * viq;
                }
            }
        }

        float eig[3] = {A[0][0], A[1][1], A[2][2]};
        // Sort descending, permuting V columns
        #pragma unroll
        for (int i = 0; i < 2; ++i)
            #pragma unroll
            for (int j = i + 1; j < 3; ++j)
                if (eig[j] > eig[i]) {
                    float tmp = eig[i]; eig[i] = eig[j]; eig[j] = tmp;
                    for (int r = 0; r < 3; ++r) {
                        tmp = V[r][i]; V[r][i] = V[r][j]; V[r][j] = tmp;
                    }
                }

        // U columns: u0 = normalize(Hs v0); u1 = GS(Hs v1); u2 = u0 x u1
        float U[3][3];
        {
            float u0[3], u1[3];
            for (int i = 0; i < 3; ++i)
                u0[i] = Hs[i][0] * V[0][0] + Hs[i][1] * V[1][0] + Hs[i][2] * V[2][0];
            const float nn0 = u0[0] * u0[0] + u0[1] * u0[1] + u0[2] * u0[2];
            if (nn0 > 1e-40f) { const float r = rsqrtf(nn0); u0[0] *= r; u0[1] *= r; u0[2] *= r; }
            else { u0[0] = 1; u0[1] = 0; u0[2] = 0; }

            for (int i = 0; i < 3; ++i)
                u1[i] = Hs[i][0] * V[0][1] + Hs[i][1] * V[1][1] + Hs[i][2] * V[2][1];
            const float d01 = u1[0] * u0[0] + u1[1] * u0[1] + u1[2] * u0[2];
            u1[0] -= d01 * u0[0]; u1[1] -= d01 * u0[1]; u1[2] -= d01 * u0[2];
            const float nn1 = u1[0] * u1[0] + u1[1] * u1[1] + u1[2] * u1[2];
            if (nn1 > 1e-40f) { const float r = rsqrtf(nn1); u1[0] *= r; u1[1] *= r; u1[2] *= r; }
            else {
                // pick any unit vector orthogonal to u0
                const float ax = fabsf(u0[0]), ay = fabsf(u0[1]), az = fabsf(u0[2]);
                float e[3] = {0, 0, 0};
                if (ax <= ay && ax <= az) e[0] = 1;
                else if (ay <= az) e[1] = 1;
                else e[2] = 1;
                u1[0] = u0[1] * e[2] - u0[2] * e[1];
                u1[1] = u0[2] * e[0] - u0[0] * e[2];
                u1[2] = u0[0] * e[1] - u0[1] * e[0];
                const float rn = rsqrtf(u1[0] * u1[0] + u1[1] * u1[1] + u1[2] * u1[2]);
                u1[0] *= rn; u1[1] *= rn; u1[2] *= rn;
            }
            const float u2[3] = { u0[1] * u1[2] - u0[2] * u1[1],
                                  u0[2] * u1[0] - u0[0] * u1[2],
                                  u0[0] * u1[1] - u0[1] * u1[0] };
            for (int i = 0; i < 3; ++i) {
                U[i][0] = u0[i]; U[i][1] = u1[i]; U[i][2] = u2[i];
            }
        }

        const float detV =
            V[0][0] * (V[1][1] * V[2][2] - V[1][2] * V[2][1]) -
            V[0][1] * (V[1][0] * V[2][2] - V[1][2] * V[2][0]) +
            V[0][2] * (V[1][0] * V[2][1] - V[1][1] * V[2][0]);
        const float detU =
            U[0][0] * (U[1][1] * U[2][2] - U[1][2] * U[2][1]) -
            U[0][1] * (U[1][0] * U[2][2] - U[1][2] * U[2][0]) +
            U[0][2] * (U[1][0] * U[2][1] - U[1][1] * U[2][0]);
        const float d = detV * detU;   // det(V U^T)

        // R = V diag(1,1,d) U^T
        float R[3][3];
        for (int i = 0; i < 3; ++i)
            for (int j = 0; j < 3; ++j)
                R[i][j] = V[i][0] * U[j][0] + V[i][1] * U[j][1] + d * V[i][2] * U[j][2];

        // t = c_t - R c_s
        float tv[3];
        for (int i = 0; i < 3; ++i)
            tv[i] = bc[3 + i] - (R[i][0] * bc[0] + R[i][1] * bc[1] + R[i][2] * bc[2]);

        // Output: R (B*9) then t (B*3)
        for (int i = 0; i < 3; ++i)
            for (int j = 0; j < 3; ++j)
                out[b * 9 + i * 3 + j] = R[i][j];
        for (int i = 0; i < 3; ++i)
            out[BB * 9 + b * 3 + i] = tv[i];
    }
}

extern "C" void kernel_launch(void* const* d_in, const int* in_sizes, int n_in,
                              void* d_out, int out_size)
{
    const float* pts_x = (const float*)d_in[0];
    const float* pts_y = (const float*)d_in[1];
    const float* gam_x = (const float*)d_in[2];
    const float* gam_y = (const float*)d_in[3];

    dim3 grid1(CHUNKS, BB, 2);
    stage1_kernel<<<grid1, 256>>>(pts_x, pts_y, gam_x, gam_y);
    stage2_kernel<<<BB, KK>>>((float*)d_out);
}